// round 11
// baseline (speedup 1.0000x reference)
#include <cuda_runtime.h>
#include <math.h>
#include <stdint.h>

#define BB 8
#define CC 96
#define NN 3136
#define KK 9
#define KI 12     // per-thread candidate list length (pass 1)
#define NCAND 96  // 8 lists * KI per row

// ---------------- scratch (device globals: no allocations allowed) ----------
__device__ float    g_y1[BB*CC*NN];
__device__ float    g_y1t[BB*NN*CC];
__device__ float    g_xnt[BB*NN*CC];     // fp32 normalized features (rescore)
__device__ unsigned g_xtf[BB*NN*CC];     // tf32 bits, column-permuted (pass 1)
__device__ int      g_cand[BB*NN*NCAND];
__device__ int      g_idx[BB*NN*KK];
__device__ float    g_cat[BB*2*CC*NN];
__device__ float    g_y2[BB*2*CC*NN];
__device__ float    g_t [BB*4*CC*NN];
__device__ float    g_s1[BB*CC*NN];
__device__ float    g_s2[BB*CC*NN];

// ---------------- 1x1-conv GEMM: out[b,o,n] = sum_c W[o,c] in[b,c,n] + bias[o]
#define GTO 96
#define GTN 128
#define GTK 32
__global__ void __launch_bounds__(256, 2)
gemm_bias_kernel(const float* __restrict__ in, const float* __restrict__ W,
                 const float* __restrict__ bias, float* __restrict__ out,
                 int Cin, int Cout)
{
    int b  = blockIdx.z;
    int o0 = blockIdx.y * GTO;
    int n0 = blockIdx.x * GTN;
    const float* inb = in + (size_t)b * Cin * NN;
    float* outb      = out + (size_t)b * Cout * NN;

    __shared__ float Ws[GTK][GTO + 4];
    __shared__ float Is[GTK][GTN];

    int tid = threadIdx.x;
    int tx = tid & 31;
    int ty = tid >> 5;

    float acc[12][4];
    #pragma unroll
    for (int i = 0; i < 12; i++)
        #pragma unroll
        for (int j = 0; j < 4; j++) acc[i][j] = 0.f;

    for (int k0 = 0; k0 < Cin; k0 += GTK) {
        for (int i = tid; i < GTO * GTK; i += 256) {
            int o = i >> 5, k = i & 31;
            Ws[k][o] = W[(size_t)(o0 + o) * Cin + k0 + k];
        }
        for (int i = tid; i < GTK * GTN / 4; i += 256) {
            int k = i >> 5, n4 = i & 31;
            int gn = n0 + n4 * 4;
            float4 v = make_float4(0.f, 0.f, 0.f, 0.f);
            if (gn < NN) v = *(const float4*)&inb[(size_t)(k0 + k) * NN + gn];
            *(float4*)&Is[k][n4 * 4] = v;
        }
        __syncthreads();
        #pragma unroll 4
        for (int k = 0; k < GTK; k++) {
            float a[12];
            #pragma unroll
            for (int q = 0; q < 3; q++)
                *(float4*)&a[q * 4] = *(const float4*)&Ws[k][ty * 12 + q * 4];
            float4 bv = *(const float4*)&Is[k][tx * 4];
            #pragma unroll
            for (int i = 0; i < 12; i++) {
                acc[i][0] += a[i] * bv.x; acc[i][1] += a[i] * bv.y;
                acc[i][2] += a[i] * bv.z; acc[i][3] += a[i] * bv.w;
            }
        }
        __syncthreads();
    }
    #pragma unroll
    for (int i = 0; i < 12; i++) {
        int o = o0 + ty * 12 + i;
        float bb = bias[o];
        #pragma unroll
        for (int j = 0; j < 4; j++) {
            int n = n0 + tx * 4 + j;
            if (n < NN) outb[(size_t)o * NN + n] = acc[i][j] + bb;
        }
    }
}

// ---------------- instance norm over N per (b,c) row, with fused epilogues
// EPI: 0=none, 1=gelu(exact), 2=relu, 3=add residual
#define NN4 (NN/4)
template<int EPI>
__global__ void inorm_kernel(const float* __restrict__ in, float* __restrict__ out,
                             const float* __restrict__ res)
{
    int row = blockIdx.x;
    const float4* x4 = (const float4*)(in + (size_t)row * NN);
    float4* y4       = (float4*)(out + (size_t)row * NN);
    const float4* r4 = res ? (const float4*)(res + (size_t)row * NN) : nullptr;

    float s = 0.f, ss = 0.f;
    for (int i = threadIdx.x; i < NN4; i += blockDim.x) {
        float4 v = x4[i];
        s  += v.x + v.y + v.z + v.w;
        ss += v.x*v.x + v.y*v.y + v.z*v.z + v.w*v.w;
    }
    __shared__ float red[2][32];
    #pragma unroll
    for (int o = 16; o; o >>= 1) {
        s  += __shfl_down_sync(0xffffffffu, s,  o);
        ss += __shfl_down_sync(0xffffffffu, ss, o);
    }
    int wid = threadIdx.x >> 5, lid = threadIdx.x & 31;
    if (!lid) { red[0][wid] = s; red[1][wid] = ss; }
    __syncthreads();
    if (wid == 0) {
        s  = (lid < (int)(blockDim.x >> 5)) ? red[0][lid] : 0.f;
        ss = (lid < (int)(blockDim.x >> 5)) ? red[1][lid] : 0.f;
        #pragma unroll
        for (int o = 16; o; o >>= 1) {
            s  += __shfl_down_sync(0xffffffffu, s,  o);
            ss += __shfl_down_sync(0xffffffffu, ss, o);
        }
        if (!lid) { red[0][0] = s; red[1][0] = ss; }
    }
    __syncthreads();
    float mean = red[0][0] * (1.f / NN);
    float var  = red[1][0] * (1.f / NN) - mean * mean;
    float rstd = rsqrtf(var + 1e-5f);
    for (int i = threadIdx.x; i < NN4; i += blockDim.x) {
        float4 v = x4[i];
        float o0 = (v.x - mean) * rstd, o1 = (v.y - mean) * rstd;
        float o2 = (v.z - mean) * rstd, o3 = (v.w - mean) * rstd;
        if (EPI == 1) {
            o0 = 0.5f*o0*(1.f + erff(o0*0.70710678118654752f));
            o1 = 0.5f*o1*(1.f + erff(o1*0.70710678118654752f));
            o2 = 0.5f*o2*(1.f + erff(o2*0.70710678118654752f));
            o3 = 0.5f*o3*(1.f + erff(o3*0.70710678118654752f));
        } else if (EPI == 2) {
            o0 = fmaxf(o0, 0.f); o1 = fmaxf(o1, 0.f);
            o2 = fmaxf(o2, 0.f); o3 = fmaxf(o3, 0.f);
        } else if (EPI == 3) {
            float4 r = r4[i];
            o0 += r.x; o1 += r.y; o2 += r.z; o3 += r.w;
        }
        y4[i] = make_float4(o0, o1, o2, o3);
    }
}

__device__ __forceinline__ unsigned f2tf(float v) {
    unsigned r;
    asm("cvt.rna.tf32.f32 %0, %1;" : "=r"(r) : "f"(v));
    return r;
}

// ---------------- per-pixel L2 norm -> fp32 [b][n][c], permuted tf32 plane,
//                  and raw transposed features (fused transpose)
__global__ void colnorm_t_kernel(const float* __restrict__ y1, float* __restrict__ xnt,
                                 unsigned* __restrict__ xtf, float* __restrict__ y1t)
{
    int b = blockIdx.y;
    int n = blockIdx.x * blockDim.x + threadIdx.x;
    if (n >= NN) return;
    const float* p = y1 + (size_t)b * CC * NN + n;
    float v[CC];
    float s = 0.f;
    #pragma unroll
    for (int c = 0; c < CC; c++) { v[c] = p[(size_t)c * NN]; s += v[c] * v[c]; }
    float rn = 1.f / fmaxf(sqrtf(s), 1e-12f);
    float4* q = (float4*)(xnt + ((size_t)b * NN + n) * CC);
    float4* qr = (float4*)(y1t + ((size_t)b * NN + n) * CC);
    #pragma unroll
    for (int cq = 0; cq < CC/4; cq++) {
        q[cq]  = make_float4(v[4*cq]*rn, v[4*cq+1]*rn, v[4*cq+2]*rn, v[4*cq+3]*rn);
        qr[cq] = make_float4(v[4*cq], v[4*cq+1], v[4*cq+2], v[4*cq+3]);
    }
    // permuted tf32 plane: element c -> (c&~7) + 2*(c&3) + ((c>>2)&1)
    unsigned pw[CC];
    #pragma unroll
    for (int c = 0; c < CC; c++) {
        int pc = (c & ~7) + 2 * (c & 3) + ((c >> 2) & 1);
        pw[pc] = f2tf(v[c] * rn);
    }
    uint4* qt = (uint4*)(xtf + ((size_t)b * NN + n) * CC);
    #pragma unroll
    for (int g = 0; g < CC/4; g++)
        qt[g] = make_uint4(pw[4*g], pw[4*g+1], pw[4*g+2], pw[4*g+3]);
}

// ---------------- PASS 1: tf32 MMA distance GEMM + per-thread top-12 candidates
// score(n,m) = rp[n,m] - 2*dot(xn_n, xn_m)  (sq terms == 1; ordering identical)
#define KTR 64
#define KTC 128
#define NT  ((NN + KTC - 1) / KTC)            // 25
#define AST 104                               // smem row stride, conflict-free LDS.64
#define SMEM_KNN ((KTR*AST + KTC*AST) * 4)    // A + B (79,872 B)

__device__ __forceinline__ void mma_tf32(float c[4],
    unsigned a0, unsigned a1, unsigned a2, unsigned a3, unsigned b0, unsigned b1)
{
    asm volatile(
        "mma.sync.aligned.m16n8k8.row.col.f32.tf32.tf32.f32 "
        "{%0,%1,%2,%3},{%4,%5,%6,%7},{%8,%9},{%0,%1,%2,%3};"
        : "+f"(c[0]), "+f"(c[1]), "+f"(c[2]), "+f"(c[3])
        : "r"(a0), "r"(a1), "r"(a2), "r"(a3), "r"(b0), "r"(b1));
}

__device__ __forceinline__ void ins12(float (&bv)[KI], int (&bi)[KI], float s, int c)
{
    if (s < bv[KI-1]) {
        bv[KI-1] = s; bi[KI-1] = c;
        #pragma unroll
        for (int k = KI-1; k > 0; k--) {
            if (bv[k] < bv[k-1]) {
                float tv = bv[k]; bv[k] = bv[k-1]; bv[k-1] = tv;
                int   ti = bi[k]; bi[k] = bi[k-1]; bi[k-1] = ti;
            }
        }
    }
}

__global__ void __launch_bounds__(256, 2)
knn_mma_kernel(const unsigned* __restrict__ xtf, const float* __restrict__ rp,
               int* __restrict__ cand)
{
    extern __shared__ unsigned smu[];
    unsigned* As = smu;                 // [KTR][AST]
    unsigned* Bs = smu + KTR * AST;     // [KTC][AST]

    int b  = blockIdx.y;
    int r0 = blockIdx.x * KTR;          // NN = 49*64 exact
    const uint4* xb4 = (const uint4*)(xtf + (size_t)b * NN * CC);   // 24 uint4/row
    int tid  = threadIdx.x;
    int warp = tid >> 5, lane = tid & 31;
    int g = lane >> 2, th = lane & 3;
    int wrow = (warp >> 1) * 16;
    int cw   = warp & 1;

    // power-of-2 staging decomposition: row = tid>>2, quad = tid&3
    int srow = tid >> 2;                // 0..63
    int sq4  = tid & 3;                 // 0..3

    // ---- stage A tile (64 rows x 24 uint4), shift/mask addressing only
    {
        const uint4* src = xb4 + (size_t)(r0 + srow) * 24;
        unsigned* dst = &As[srow * AST];
        #pragma unroll
        for (int j = 0; j < 6; j++) {
            int q = sq4 + 4 * j;
            *(uint4*)&dst[q * 4] = __ldg(src + q);
        }
    }

    float best0[KI], best1[KI]; int bidx0[KI], bidx1[KI];
    #pragma unroll
    for (int k = 0; k < KI; k++) {
        best0[k] = 3.4e38f; bidx0[k] = 0;
        best1[k] = 3.4e38f; bidx1[k] = 0;
    }
    float thr0 = 3.4e38f, thr1 = 3.4e38f;

    int r1 = r0 + wrow + g, r2 = r1 + 8;

    for (int t = 0; t < NT; t++) {
        int m0 = t * KTC;
        __syncthreads();   // prev compute done before overwriting Bs
        #pragma unroll
        for (int p = 0; p < 2; p++) {
            int br = srow + 64 * p;
            int src = m0 + br; if (src >= NN) src = NN - 1;
            const uint4* sp = xb4 + (size_t)src * 24;
            unsigned* dst = &Bs[br * AST];
            #pragma unroll
            for (int j = 0; j < 6; j++) {
                int q = sq4 + 4 * j;
                *(uint4*)&dst[q * 4] = __ldg(sp + q);
            }
        }
        __syncthreads();

        float C[8][4];
        #pragma unroll
        for (int f = 0; f < 8; f++)
            #pragma unroll
            for (int j = 0; j < 4; j++) C[f][j] = 0.f;

        for (int ks = 0; ks < 12; ks++) {
            int k0 = ks * 8;
            int offA = (wrow + g) * AST + k0 + 2*th;
            uint2 a01 = *(const uint2*)&As[offA];
            uint2 a23 = *(const uint2*)&As[offA + 8*AST];
            #pragma unroll
            for (int f = 0; f < 8; f++) {
                int offB = (cw*64 + f*8 + g) * AST + k0 + 2*th;
                uint2 bv = *(const uint2*)&Bs[offB];
                mma_tf32(C[f], a01.x, a23.x, a01.y, a23.y, bv.x, bv.y);
            }
        }

        // ---- selection with threshold pre-filter (rare slow path)
        #pragma unroll
        for (int f = 0; f < 8; f++) {
            int nb = cw * 64 + f * 8;
            if (m0 + nb < NN) {
                int gm = m0 + nb + 2 * th;
                float2 p1 = *(const float2*)&rp[(size_t)r1 * NN + gm];
                float2 p2 = *(const float2*)&rp[(size_t)r2 * NN + gm];
                float s0 = p1.x - 2.f * C[f][0];
                float s1 = p1.y - 2.f * C[f][1];
                float s2 = p2.x - 2.f * C[f][2];
                float s3 = p2.y - 2.f * C[f][3];
                if (fminf(s0, s1) < thr0) {
                    ins12(best0, bidx0, s0, gm);
                    ins12(best0, bidx0, s1, gm + 1);
                    thr0 = best0[KI-1];
                }
                if (fminf(s2, s3) < thr1) {
                    ins12(best1, bidx1, s2, gm);
                    ins12(best1, bidx1, s3, gm + 1);
                    thr1 = best1[KI-1];
                }
            }
        }
    }

    // ---- write candidate lists (8 lists of KI per row, disjoint columns)
    int list = cw * 4 + th;
    {
        int* op = cand + ((size_t)b * NN + r1) * NCAND + list * KI;
        #pragma unroll
        for (int k = 0; k < KI; k++) op[k] = bidx0[k];
    }
    {
        int* op = cand + ((size_t)b * NN + r2) * NCAND + list * KI;
        #pragma unroll
        for (int k = 0; k < KI; k++) op[k] = bidx1[k];
    }
}

// ---------------- PASS 2: exact fp32 rescoring, block-per-pixel, coalesced
#define CRS (CC + 1)   // 97: conflict-free smem reads
__global__ void __launch_bounds__(128)
rescore_kernel(const float* __restrict__ xnt, const float* __restrict__ rp,
               const int* __restrict__ cand, int* __restrict__ idx)
{
    int n = blockIdx.x, b = blockIdx.y;
    int tid = threadIdx.x;
    int lane = tid & 31;

    __shared__ float crow[NCAND][CRS];
    __shared__ float own[CC];
    __shared__ float sc[NCAND];
    __shared__ int   cidx[NCAND];

    const float* xb = xnt + (size_t)b * NN * CC;

    if (tid < CC/4)
        *(float4*)&own[tid * 4] = *(const float4*)&xb[(size_t)n * CC + tid * 4];
    if (tid < NCAND)
        cidx[tid] = cand[((size_t)b * NN + n) * NCAND + tid];
    __syncthreads();

    // stage 96 candidate rows: c = (tid>>2)+32p, q = (tid&3)+4j — shift/mask only
    {
        int c0 = tid >> 2, q4 = tid & 3;
        #pragma unroll
        for (int p = 0; p < 3; p++) {
            int c = c0 + 32 * p;
            const float4* sp = (const float4*)&xb[(size_t)cidx[c] * CC];
            #pragma unroll
            for (int j = 0; j < 6; j++) {
                int q = q4 + 4 * j;
                float4 v = __ldg(sp + q);
                crow[c][q*4 + 0] = v.x; crow[c][q*4 + 1] = v.y;
                crow[c][q*4 + 2] = v.z; crow[c][q*4 + 3] = v.w;
            }
        }
    }
    __syncthreads();

    if (tid < NCAND) {
        float dot = 0.f;
        #pragma unroll
        for (int q = 0; q < CC; q++) dot += own[q] * crow[tid][q];
        sc[tid] = __ldg(&rp[(size_t)n * NN + cidx[tid]]) - 2.f * dot;
    }
    __syncthreads();

    if (tid < 32) {
        float v[3]; int id[3];
        #pragma unroll
        for (int s = 0; s < 3; s++) { v[s] = sc[s*32 + lane]; id[s] = cidx[s*32 + lane]; }
        int* op = idx + ((size_t)b * NN + n) * KK;
        #pragma unroll 1
        for (int k = 0; k < KK; k++) {
            float bv = v[0]; int bi = id[0];
            if (v[1] < bv || (v[1] == bv && id[1] < bi)) { bv = v[1]; bi = id[1]; }
            if (v[2] < bv || (v[2] == bv && id[2] < bi)) { bv = v[2]; bi = id[2]; }
            #pragma unroll
            for (int o = 16; o; o >>= 1) {
                float ov = __shfl_down_sync(0xffffffffu, bv, o);
                int   oi = __shfl_down_sync(0xffffffffu, bi, o);
                if (ov < bv || (ov == bv && oi < bi)) { bv = ov; bi = oi; }
            }
            bi = __shfl_sync(0xffffffffu, bi, 0);
            if (lane == 0) op[k] = bi;
            #pragma unroll
            for (int s = 0; s < 3; s++) if (id[s] == bi) v[s] = 3.5e38f;
        }
    }
}

// ---------------- max-relative gather (from transposed features) + interleaved concat
__global__ void gather2_kernel(const float* __restrict__ y1t, const int* __restrict__ idx,
                               float* __restrict__ cat)
{
    int b = blockIdx.y;
    int n = blockIdx.x * blockDim.x + threadIdx.x;
    if (n >= NN) return;
    const int* ib = idx + ((size_t)b * NN + n) * KK;
    int j[KK];
    #pragma unroll
    for (int k = 0; k < KK; k++) j[k] = ib[k];

    const float4* base = (const float4*)(y1t + (size_t)b * NN * CC);
    const float4* own  = base + (size_t)n * (CC/4);
    float* cb = cat + (size_t)b * 2 * CC * NN + n;

    #pragma unroll 2
    for (int cc = 0; cc < CC/4; cc++) {
        float4 o = own[cc];
        float4 m = base[(size_t)j[0] * (CC/4) + cc];
        #pragma unroll
        for (int k = 1; k < KK; k++) {
            float4 v = base[(size_t)j[k] * (CC/4) + cc];
            m.x = fmaxf(m.x, v.x); m.y = fmaxf(m.y, v.y);
            m.z = fmaxf(m.z, v.z); m.w = fmaxf(m.w, v.w);
        }
        cb[(size_t)(8*cc + 0) * NN] = o.x;
        cb[(size_t)(8*cc + 1) * NN] = m.x - o.x;
        cb[(size_t)(8*cc + 2) * NN] = o.y;
        cb[(size_t)(8*cc + 3) * NN] = m.y - o.y;
        cb[(size_t)(8*cc + 4) * NN] = o.z;
        cb[(size_t)(8*cc + 5) * NN] = m.z - o.z;
        cb[(size_t)(8*cc + 6) * NN] = o.w;
        cb[(size_t)(8*cc + 7) * NN] = m.w - o.w;
    }
}

// ---------------- host orchestration -----------------------------------------
static void run_grapher(const float* X, const float* rp,
                        const float* fc1w, const float* fc1b,
                        const float* mrw,  const float* mrb,
                        const float* fc2w, const float* fc2b,
                        float* out,
                        float* y1, float* y1t, float* xnt, unsigned* xtf,
                        int* cd, int* idx, float* cat, float* y2, float* t)
{
    dim3 gA((NN + GTN - 1) / GTN, CC / GTO, BB);
    gemm_bias_kernel<<<gA, 256>>>(X, fc1w, fc1b, y1, CC, CC);
    inorm_kernel<0><<<BB * CC, 256>>>(y1, y1, nullptr);
    colnorm_t_kernel<<<dim3((NN + 255) / 256, BB), 256>>>(y1, xnt, xtf, y1t);
    knn_mma_kernel<<<dim3(NN / KTR, BB), 256, SMEM_KNN>>>(xtf, rp, cd);
    rescore_kernel<<<dim3(NN, BB), 128>>>(xnt, rp, cd, idx);
    gather2_kernel<<<dim3((NN + 255) / 256, BB), 256>>>(y1t, idx, cat);
    dim3 gB((NN + GTN - 1) / GTN, 2 * CC / GTO, BB);
    gemm_bias_kernel<<<gB, 256>>>(cat, mrw, mrb, y2, 2 * CC, 2 * CC);
    inorm_kernel<1><<<BB * 2 * CC, 256>>>(y2, y2, nullptr);
    dim3 gC((NN + GTN - 1) / GTN, CC / GTO, BB);
    gemm_bias_kernel<<<gC, 256>>>(y2, fc2w, fc2b, t, 2 * CC, CC);
    inorm_kernel<3><<<BB * CC, 256>>>(t, out, X);
}

static void run_ffn(const float* X,
                    const float* w1, const float* b1,
                    const float* w2, const float* b2,
                    float* out, float* t, float* y1)
{
    dim3 gA((NN + GTN - 1) / GTN, 4 * CC / GTO, BB);
    gemm_bias_kernel<<<gA, 256>>>(X, w1, b1, t, CC, 4 * CC);
    inorm_kernel<1><<<BB * 4 * CC, 256>>>(t, t, nullptr);
    dim3 gB((NN + GTN - 1) / GTN, CC / GTO, BB);
    gemm_bias_kernel<<<gB, 256>>>(t, w2, b2, y1, 4 * CC, CC);
    inorm_kernel<3><<<BB * CC, 256>>>(y1, out, X);
}

extern "C" void kernel_launch(void* const* d_in, const int* in_sizes, int n_in,
                              void* d_out, int out_size)
{
    const float* X0 = (const float*)d_in[0];
    const float* rp = (const float*)d_in[1];

    float *y1, *y1t, *xnt, *cat, *y2, *t, *s1, *s2; int *cd, *idx; unsigned* xtf;
    cudaGetSymbolAddress((void**)&y1,  g_y1);
    cudaGetSymbolAddress((void**)&y1t, g_y1t);
    cudaGetSymbolAddress((void**)&xnt, g_xnt);
    cudaGetSymbolAddress((void**)&xtf, g_xtf);
    cudaGetSymbolAddress((void**)&cd,  g_cand);
    cudaGetSymbolAddress((void**)&idx, g_idx);
    cudaGetSymbolAddress((void**)&cat, g_cat);
    cudaGetSymbolAddress((void**)&y2,  g_y2);
    cudaGetSymbolAddress((void**)&t,   g_t);
    cudaGetSymbolAddress((void**)&s1,  g_s1);
    cudaGetSymbolAddress((void**)&s2,  g_s2);

    cudaFuncSetAttribute(knn_mma_kernel, cudaFuncAttributeMaxDynamicSharedMemorySize, SMEM_KNN);

    // grapher 1: X0 -> s1
    run_grapher(X0, rp,
                (const float*)d_in[2], (const float*)d_in[3],
                (const float*)d_in[4], (const float*)d_in[5],
                (const float*)d_in[6], (const float*)d_in[7],
                s1, y1, y1t, xnt, xtf, cd, idx, cat, y2, t);
    // ffn 1: s1 -> s2
    run_ffn(s1,
            (const float*)d_in[14], (const float*)d_in[15],
            (const float*)d_in[16], (const float*)d_in[17],
            s2, t, y1);
    // mid: relu(inorm(s2)) -> s1
    inorm_kernel<2><<<BB * CC, 256>>>(s2, s1, nullptr);
    // grapher 2: s1 -> s2
    run_grapher(s1, rp,
                (const float*)d_in[8],  (const float*)d_in[9],
                (const float*)d_in[10], (const float*)d_in[11],
                (const float*)d_in[12], (const float*)d_in[13],
                s2, y1, y1t, xnt, xtf, cd, idx, cat, y2, t);
    // ffn 2: s2 -> s1
    run_ffn(s2,
            (const float*)d_in[18], (const float*)d_in[19],
            (const float*)d_in[20], (const float*)d_in[21],
            s1, t, y1);
    // final: out = X0 + inorm(s1)
    inorm_kernel<3><<<BB * CC, 256>>>(s1, (float*)d_out, X0);
}

// round 13
// speedup vs baseline: 1.3648x; 1.3648x over previous
#include <cuda_runtime.h>
#include <math.h>
#include <stdint.h>

#define BB 8
#define CC 96
#define NN 3136
#define KK 9
#define KI 8      // per-thread candidate list length (pass 1)
#define NCAND 64  // 8 lists * KI per row

// ---------------- scratch (device globals: no allocations allowed) ----------
__device__ float    g_y1[BB*CC*NN];
__device__ float    g_y1t[BB*NN*CC];
__device__ float    g_xnt[BB*NN*CC];     // fp32 normalized features (rescore)
__device__ unsigned g_xtf[BB*NN*CC];     // tf32 bits, column-permuted (pass 1)
__device__ int      g_cand[BB*NN*NCAND];
__device__ int      g_idx[BB*NN*KK];
__device__ float    g_cat[BB*2*CC*NN];
__device__ float    g_y2[BB*2*CC*NN];
__device__ float    g_t [BB*4*CC*NN];
__device__ float    g_s1[BB*CC*NN];
__device__ float    g_s2[BB*CC*NN];

// ---------------- 1x1-conv GEMM: out[b,o,n] = sum_c W[o,c] in[b,c,n] + bias[o]
#define GTO 96
#define GTN 128
#define GTK 32
__global__ void __launch_bounds__(256, 3)
gemm_bias_kernel(const float* __restrict__ in, const float* __restrict__ W,
                 const float* __restrict__ bias, float* __restrict__ out,
                 int Cin, int Cout)
{
    int b  = blockIdx.z;
    int o0 = blockIdx.y * GTO;
    int n0 = blockIdx.x * GTN;
    const float* inb = in + (size_t)b * Cin * NN;
    float* outb      = out + (size_t)b * Cout * NN;

    __shared__ float Ws[GTK][GTO + 4];
    __shared__ float Is[GTK][GTN];

    int tid = threadIdx.x;
    int tx = tid & 31;
    int ty = tid >> 5;

    float acc[12][4];
    #pragma unroll
    for (int i = 0; i < 12; i++)
        #pragma unroll
        for (int j = 0; j < 4; j++) acc[i][j] = 0.f;

    for (int k0 = 0; k0 < Cin; k0 += GTK) {
        for (int i = tid; i < GTO * GTK; i += 256) {
            int o = i >> 5, k = i & 31;
            Ws[k][o] = W[(size_t)(o0 + o) * Cin + k0 + k];
        }
        for (int i = tid; i < GTK * GTN / 4; i += 256) {
            int k = i >> 5, n4 = i & 31;
            int gn = n0 + n4 * 4;
            float4 v = make_float4(0.f, 0.f, 0.f, 0.f);
            if (gn < NN) v = *(const float4*)&inb[(size_t)(k0 + k) * NN + gn];
            *(float4*)&Is[k][n4 * 4] = v;
        }
        __syncthreads();
        #pragma unroll 4
        for (int k = 0; k < GTK; k++) {
            float a[12];
            #pragma unroll
            for (int q = 0; q < 3; q++)
                *(float4*)&a[q * 4] = *(const float4*)&Ws[k][ty * 12 + q * 4];
            float4 bv = *(const float4*)&Is[k][tx * 4];
            #pragma unroll
            for (int i = 0; i < 12; i++) {
                acc[i][0] += a[i] * bv.x; acc[i][1] += a[i] * bv.y;
                acc[i][2] += a[i] * bv.z; acc[i][3] += a[i] * bv.w;
            }
        }
        __syncthreads();
    }
    #pragma unroll
    for (int i = 0; i < 12; i++) {
        int o = o0 + ty * 12 + i;
        float bb = bias[o];
        #pragma unroll
        for (int j = 0; j < 4; j++) {
            int n = n0 + tx * 4 + j;
            if (n < NN) outb[(size_t)o * NN + n] = acc[i][j] + bb;
        }
    }
}

// ---------------- instance norm over N per (b,c) row, with fused epilogues
// EPI: 0=none, 1=gelu(exact), 2=relu, 3=add residual
#define NN4 (NN/4)
template<int EPI>
__global__ void inorm_kernel(const float* __restrict__ in, float* __restrict__ out,
                             const float* __restrict__ res)
{
    int row = blockIdx.x;
    const float4* x4 = (const float4*)(in + (size_t)row * NN);
    float4* y4       = (float4*)(out + (size_t)row * NN);
    const float4* r4 = res ? (const float4*)(res + (size_t)row * NN) : nullptr;

    float s = 0.f, ss = 0.f;
    for (int i = threadIdx.x; i < NN4; i += blockDim.x) {
        float4 v = x4[i];
        s  += v.x + v.y + v.z + v.w;
        ss += v.x*v.x + v.y*v.y + v.z*v.z + v.w*v.w;
    }
    __shared__ float red[2][32];
    #pragma unroll
    for (int o = 16; o; o >>= 1) {
        s  += __shfl_down_sync(0xffffffffu, s,  o);
        ss += __shfl_down_sync(0xffffffffu, ss, o);
    }
    int wid = threadIdx.x >> 5, lid = threadIdx.x & 31;
    if (!lid) { red[0][wid] = s; red[1][wid] = ss; }
    __syncthreads();
    if (wid == 0) {
        s  = (lid < (int)(blockDim.x >> 5)) ? red[0][lid] : 0.f;
        ss = (lid < (int)(blockDim.x >> 5)) ? red[1][lid] : 0.f;
        #pragma unroll
        for (int o = 16; o; o >>= 1) {
            s  += __shfl_down_sync(0xffffffffu, s,  o);
            ss += __shfl_down_sync(0xffffffffu, ss, o);
        }
        if (!lid) { red[0][0] = s; red[1][0] = ss; }
    }
    __syncthreads();
    float mean = red[0][0] * (1.f / NN);
    float var  = red[1][0] * (1.f / NN) - mean * mean;
    float rstd = rsqrtf(var + 1e-5f);
    for (int i = threadIdx.x; i < NN4; i += blockDim.x) {
        float4 v = x4[i];
        float o0 = (v.x - mean) * rstd, o1 = (v.y - mean) * rstd;
        float o2 = (v.z - mean) * rstd, o3 = (v.w - mean) * rstd;
        if (EPI == 1) {
            o0 = 0.5f*o0*(1.f + erff(o0*0.70710678118654752f));
            o1 = 0.5f*o1*(1.f + erff(o1*0.70710678118654752f));
            o2 = 0.5f*o2*(1.f + erff(o2*0.70710678118654752f));
            o3 = 0.5f*o3*(1.f + erff(o3*0.70710678118654752f));
        } else if (EPI == 2) {
            o0 = fmaxf(o0, 0.f); o1 = fmaxf(o1, 0.f);
            o2 = fmaxf(o2, 0.f); o3 = fmaxf(o3, 0.f);
        } else if (EPI == 3) {
            float4 r = r4[i];
            o0 += r.x; o1 += r.y; o2 += r.z; o3 += r.w;
        }
        y4[i] = make_float4(o0, o1, o2, o3);
    }
}

__device__ __forceinline__ unsigned f2tf(float v) {
    unsigned r;
    asm("cvt.rna.tf32.f32 %0, %1;" : "=r"(r) : "f"(v));
    return r;
}

// ---------------- per-pixel L2 norm -> fp32 [b][n][c], permuted tf32 plane,
//                  and raw transposed features (fused transpose)
__global__ void colnorm_t_kernel(const float* __restrict__ y1, float* __restrict__ xnt,
                                 unsigned* __restrict__ xtf, float* __restrict__ y1t)
{
    int b = blockIdx.y;
    int n = blockIdx.x * blockDim.x + threadIdx.x;
    if (n >= NN) return;
    const float* p = y1 + (size_t)b * CC * NN + n;
    float v[CC];
    float s = 0.f;
    #pragma unroll
    for (int c = 0; c < CC; c++) { v[c] = p[(size_t)c * NN]; s += v[c] * v[c]; }
    float rn = 1.f / fmaxf(sqrtf(s), 1e-12f);
    float4* q = (float4*)(xnt + ((size_t)b * NN + n) * CC);
    float4* qr = (float4*)(y1t + ((size_t)b * NN + n) * CC);
    #pragma unroll
    for (int cq = 0; cq < CC/4; cq++) {
        q[cq]  = make_float4(v[4*cq]*rn, v[4*cq+1]*rn, v[4*cq+2]*rn, v[4*cq+3]*rn);
        qr[cq] = make_float4(v[4*cq], v[4*cq+1], v[4*cq+2], v[4*cq+3]);
    }
    // permuted tf32 plane: element c -> (c&~7) + 2*(c&3) + ((c>>2)&1)
    unsigned pw[CC];
    #pragma unroll
    for (int c = 0; c < CC; c++) {
        int pc = (c & ~7) + 2 * (c & 3) + ((c >> 2) & 1);
        pw[pc] = f2tf(v[c] * rn);
    }
    uint4* qt = (uint4*)(xtf + ((size_t)b * NN + n) * CC);
    #pragma unroll
    for (int g = 0; g < CC/4; g++)
        qt[g] = make_uint4(pw[4*g], pw[4*g+1], pw[4*g+2], pw[4*g+3]);
}

// ---------------- PASS 1: tf32 MMA distance GEMM + per-thread top-8 candidates
// score(n,m) = rp[n,m] - 2*dot(xn_n, xn_m)  (sq terms == 1; ordering identical)
#define KTR 64
#define KTC 96
#define NT  ((NN + KTC - 1) / KTC)            // 33 (last tile: 64 cols)
#define AST 104                               // smem row stride, conflict-free LDS.64
#define SMEM_KNN ((KTR*AST + KTC*AST) * 4)    // 66,560 B -> 3 CTAs/SM

__device__ __forceinline__ void mma_tf32(float c[4],
    unsigned a0, unsigned a1, unsigned a2, unsigned a3, unsigned b0, unsigned b1)
{
    asm volatile(
        "mma.sync.aligned.m16n8k8.row.col.f32.tf32.tf32.f32 "
        "{%0,%1,%2,%3},{%4,%5,%6,%7},{%8,%9},{%0,%1,%2,%3};"
        : "+f"(c[0]), "+f"(c[1]), "+f"(c[2]), "+f"(c[3])
        : "r"(a0), "r"(a1), "r"(a2), "r"(a3), "r"(b0), "r"(b1));
}

__device__ __forceinline__ void ins8(float (&bv)[KI], int (&bi)[KI], float s, int c)
{
    if (s < bv[KI-1]) {
        bv[KI-1] = s; bi[KI-1] = c;
        #pragma unroll
        for (int k = KI-1; k > 0; k--) {
            if (bv[k] < bv[k-1]) {
                float tv = bv[k]; bv[k] = bv[k-1]; bv[k-1] = tv;
                int   ti = bi[k]; bi[k] = bi[k-1]; bi[k-1] = ti;
            }
        }
    }
}

__global__ void __launch_bounds__(256, 3)
knn_mma_kernel(const unsigned* __restrict__ xtf, const float* __restrict__ rp,
               int* __restrict__ cand)
{
    extern __shared__ unsigned smu[];
    unsigned* As = smu;                 // [KTR][AST]
    unsigned* Bs = smu + KTR * AST;     // [KTC][AST]

    int b  = blockIdx.y;
    int r0 = blockIdx.x * KTR;          // NN = 49*64 exact
    const uint4* xb4 = (const uint4*)(xtf + (size_t)b * NN * CC);   // 24 uint4/row
    int tid  = threadIdx.x;
    int warp = tid >> 5, lane = tid & 31;
    int g = lane >> 2, th = lane & 3;
    int wrow = (warp >> 1) * 16;
    int cw   = warp & 1;                // column half (48 cols each)

    int srow = tid >> 2;                // 0..63
    int sq4  = tid & 3;                 // 0..3

    // ---- stage A tile (64 rows x 24 uint4)
    {
        const uint4* src = xb4 + (size_t)(r0 + srow) * 24;
        unsigned* dst = &As[srow * AST];
        #pragma unroll
        for (int j = 0; j < 6; j++) {
            int q = sq4 + 4 * j;
            *(uint4*)&dst[q * 4] = __ldg(src + q);
        }
    }

    float best0[KI], best1[KI]; int bidx0[KI], bidx1[KI];
    #pragma unroll
    for (int k = 0; k < KI; k++) {
        best0[k] = 3.4e38f; bidx0[k] = 0;
        best1[k] = 3.4e38f; bidx1[k] = 0;
    }

    int r1 = r0 + wrow + g, r2 = r1 + 8;

    for (int t = 0; t < NT; t++) {
        int m0 = t * KTC;
        __syncthreads();   // prev compute done before overwriting Bs
        #pragma unroll
        for (int p = 0; p < 2; p++) {
            int br = srow + (p << 6);
            if (br < KTC) {
                int src = m0 + br; if (src >= NN) src = NN - 1;
                const uint4* sp = xb4 + (size_t)src * 24;
                unsigned* dst = &Bs[br * AST];
                #pragma unroll
                for (int j = 0; j < 6; j++) {
                    int q = sq4 + 4 * j;
                    *(uint4*)&dst[q * 4] = __ldg(sp + q);
                }
            }
        }
        __syncthreads();

        float C[6][4];
        #pragma unroll
        for (int f = 0; f < 6; f++)
            #pragma unroll
            for (int j = 0; j < 4; j++) C[f][j] = 0.f;

        for (int ks = 0; ks < 12; ks++) {
            int k0 = ks * 8;
            int offA = (wrow + g) * AST + k0 + 2*th;
            uint2 a01 = *(const uint2*)&As[offA];
            uint2 a23 = *(const uint2*)&As[offA + 8*AST];
            #pragma unroll
            for (int f = 0; f < 6; f++) {
                int offB = (cw*48 + f*8 + g) * AST + k0 + 2*th;
                uint2 bv = *(const uint2*)&Bs[offB];
                mma_tf32(C[f], a01.x, a23.x, a01.y, a23.y, bv.x, bv.y);
            }
        }

        // ---- selection straight from fragments
        #pragma unroll
        for (int f = 0; f < 6; f++) {
            int nb = cw * 48 + f * 8;
            if (m0 + nb < NN) {
                int gm = m0 + nb + 2 * th;
                float2 p1 = *(const float2*)&rp[(size_t)r1 * NN + gm];
                float2 p2 = *(const float2*)&rp[(size_t)r2 * NN + gm];
                ins8(best0, bidx0, p1.x - 2.f * C[f][0], gm);
                ins8(best0, bidx0, p1.y - 2.f * C[f][1], gm + 1);
                ins8(best1, bidx1, p2.x - 2.f * C[f][2], gm);
                ins8(best1, bidx1, p2.y - 2.f * C[f][3], gm + 1);
            }
        }
    }

    // ---- write candidate lists (8 lists of KI per row, disjoint columns)
    int list = cw * 4 + th;
    {
        int* op = cand + ((size_t)b * NN + r1) * NCAND + list * KI;
        #pragma unroll
        for (int k = 0; k < KI; k++) op[k] = bidx0[k];
    }
    {
        int* op = cand + ((size_t)b * NN + r2) * NCAND + list * KI;
        #pragma unroll
        for (int k = 0; k < KI; k++) op[k] = bidx1[k];
    }
}

// ---------------- PASS 2: exact fp32 rescoring, block-per-pixel, coalesced
#define CRS (CC + 1)   // 97: conflict-free smem reads
__global__ void __launch_bounds__(128)
rescore_kernel(const float* __restrict__ xnt, const float* __restrict__ rp,
               const int* __restrict__ cand, int* __restrict__ idx)
{
    int n = blockIdx.x, b = blockIdx.y;
    int tid = threadIdx.x;
    int lane = tid & 31;

    __shared__ float crow[NCAND][CRS];
    __shared__ float own[CC];
    __shared__ float sc[NCAND];
    __shared__ int   cidx[NCAND];

    const float* xb = xnt + (size_t)b * NN * CC;

    if (tid < CC/4)
        *(float4*)&own[tid * 4] = *(const float4*)&xb[(size_t)n * CC + tid * 4];
    if (tid < NCAND)
        cidx[tid] = cand[((size_t)b * NN + n) * NCAND + tid];
    __syncthreads();

    // stage 64 candidate rows: c = tid>>1, q = (tid&1)+2j — shift/mask only
    {
        int c = tid >> 1, q1 = tid & 1;
        const float4* sp = (const float4*)&xb[(size_t)cidx[c] * CC];
        #pragma unroll
        for (int j = 0; j < 12; j++) {
            int q = q1 + 2 * j;
            float4 v = __ldg(sp + q);
            crow[c][q*4 + 0] = v.x; crow[c][q*4 + 1] = v.y;
            crow[c][q*4 + 2] = v.z; crow[c][q*4 + 3] = v.w;
        }
    }
    __syncthreads();

    if (tid < NCAND) {
        float dot = 0.f;
        #pragma unroll
        for (int q = 0; q < CC; q++) dot += own[q] * crow[tid][q];
        sc[tid] = __ldg(&rp[(size_t)n * NN + cidx[tid]]) - 2.f * dot;
    }
    __syncthreads();

    if (tid < 32) {
        float v[2]; int id[2];
        #pragma unroll
        for (int s = 0; s < 2; s++) { v[s] = sc[s*32 + lane]; id[s] = cidx[s*32 + lane]; }
        int* op = idx + ((size_t)b * NN + n) * KK;
        #pragma unroll 1
        for (int k = 0; k < KK; k++) {
            float bv = v[0]; int bi = id[0];
            if (v[1] < bv || (v[1] == bv && id[1] < bi)) { bv = v[1]; bi = id[1]; }
            #pragma unroll
            for (int o = 16; o; o >>= 1) {
                float ov = __shfl_down_sync(0xffffffffu, bv, o);
                int   oi = __shfl_down_sync(0xffffffffu, bi, o);
                if (ov < bv || (ov == bv && oi < bi)) { bv = ov; bi = oi; }
            }
            bi = __shfl_sync(0xffffffffu, bi, 0);
            if (lane == 0) op[k] = bi;
            #pragma unroll
            for (int s = 0; s < 2; s++) if (id[s] == bi) v[s] = 3.5e38f;
        }
    }
}

// ---------------- max-relative gather (from transposed features) + interleaved concat
__global__ void gather2_kernel(const float* __restrict__ y1t, const int* __restrict__ idx,
                               float* __restrict__ cat)
{
    int b = blockIdx.y;
    int n = blockIdx.x * blockDim.x + threadIdx.x;
    if (n >= NN) return;
    const int* ib = idx + ((size_t)b * NN + n) * KK;
    int j[KK];
    #pragma unroll
    for (int k = 0; k < KK; k++) j[k] = ib[k];

    const float4* base = (const float4*)(y1t + (size_t)b * NN * CC);
    const float4* own  = base + (size_t)n * (CC/4);
    float* cb = cat + (size_t)b * 2 * CC * NN + n;

    #pragma unroll 2
    for (int cc = 0; cc < CC/4; cc++) {
        float4 o = own[cc];
        float4 m = base[(size_t)j[0] * (CC/4) + cc];
        #pragma unroll
        for (int k = 1; k < KK; k++) {
            float4 v = base[(size_t)j[k] * (CC/4) + cc];
            m.x = fmaxf(m.x, v.x); m.y = fmaxf(m.y, v.y);
            m.z = fmaxf(m.z, v.z); m.w = fmaxf(m.w, v.w);
        }
        cb[(size_t)(8*cc + 0) * NN] = o.x;
        cb[(size_t)(8*cc + 1) * NN] = m.x - o.x;
        cb[(size_t)(8*cc + 2) * NN] = o.y;
        cb[(size_t)(8*cc + 3) * NN] = m.y - o.y;
        cb[(size_t)(8*cc + 4) * NN] = o.z;
        cb[(size_t)(8*cc + 5) * NN] = m.z - o.z;
        cb[(size_t)(8*cc + 6) * NN] = o.w;
        cb[(size_t)(8*cc + 7) * NN] = m.w - o.w;
    }
}

// ---------------- host orchestration -----------------------------------------
static void run_grapher(const float* X, const float* rp,
                        const float* fc1w, const float* fc1b,
                        const float* mrw,  const float* mrb,
                        const float* fc2w, const float* fc2b,
                        float* out,
                        float* y1, float* y1t, float* xnt, unsigned* xtf,
                        int* cd, int* idx, float* cat, float* y2, float* t)
{
    dim3 gA((NN + GTN - 1) / GTN, CC / GTO, BB);
    gemm_bias_kernel<<<gA, 256>>>(X, fc1w, fc1b, y1, CC, CC);
    inorm_kernel<0><<<BB * CC, 256>>>(y1, y1, nullptr);
    colnorm_t_kernel<<<dim3((NN + 255) / 256, BB), 256>>>(y1, xnt, xtf, y1t);
    knn_mma_kernel<<<dim3(NN / KTR, BB), 256, SMEM_KNN>>>(xtf, rp, cd);
    rescore_kernel<<<dim3(NN, BB), 128>>>(xnt, rp, cd, idx);
    gather2_kernel<<<dim3((NN + 255) / 256, BB), 256>>>(y1t, idx, cat);
    dim3 gB((NN + GTN - 1) / GTN, 2 * CC / GTO, BB);
    gemm_bias_kernel<<<gB, 256>>>(cat, mrw, mrb, y2, 2 * CC, 2 * CC);
    inorm_kernel<1><<<BB * 2 * CC, 256>>>(y2, y2, nullptr);
    dim3 gC((NN + GTN - 1) / GTN, CC / GTO, BB);
    gemm_bias_kernel<<<gC, 256>>>(y2, fc2w, fc2b, t, 2 * CC, CC);
    inorm_kernel<3><<<BB * CC, 256>>>(t, out, X);
}

static void run_ffn(const float* X,
                    const float* w1, const float* b1,
                    const float* w2, const float* b2,
                    float* out, float* t, float* y1)
{
    dim3 gA((NN + GTN - 1) / GTN, 4 * CC / GTO, BB);
    gemm_bias_kernel<<<gA, 256>>>(X, w1, b1, t, CC, 4 * CC);
    inorm_kernel<1><<<BB * 4 * CC, 256>>>(t, t, nullptr);
    dim3 gB((NN + GTN - 1) / GTN, CC / GTO, BB);
    gemm_bias_kernel<<<gB, 256>>>(t, w2, b2, y1, 4 * CC, CC);
    inorm_kernel<3><<<BB * CC, 256>>>(y1, out, X);
}

extern "C" void kernel_launch(void* const* d_in, const int* in_sizes, int n_in,
                              void* d_out, int out_size)
{
    const float* X0 = (const float*)d_in[0];
    const float* rp = (const float*)d_in[1];

    float *y1, *y1t, *xnt, *cat, *y2, *t, *s1, *s2; int *cd, *idx; unsigned* xtf;
    cudaGetSymbolAddress((void**)&y1,  g_y1);
    cudaGetSymbolAddress((void**)&y1t, g_y1t);
    cudaGetSymbolAddress((void**)&xnt, g_xnt);
    cudaGetSymbolAddress((void**)&xtf, g_xtf);
    cudaGetSymbolAddress((void**)&cd,  g_cand);
    cudaGetSymbolAddress((void**)&idx, g_idx);
    cudaGetSymbolAddress((void**)&cat, g_cat);
    cudaGetSymbolAddress((void**)&y2,  g_y2);
    cudaGetSymbolAddress((void**)&t,   g_t);
    cudaGetSymbolAddress((void**)&s1,  g_s1);
    cudaGetSymbolAddress((void**)&s2,  g_s2);

    cudaFuncSetAttribute(knn_mma_kernel, cudaFuncAttributeMaxDynamicSharedMemorySize, SMEM_KNN);

    // grapher 1: X0 -> s1
    run_grapher(X0, rp,
                (const float*)d_in[2], (const float*)d_in[3],
                (const float*)d_in[4], (const float*)d_in[5],
                (const float*)d_in[6], (const float*)d_in[7],
                s1, y1, y1t, xnt, xtf, cd, idx, cat, y2, t);
    // ffn 1: s1 -> s2
    run_ffn(s1,
            (const float*)d_in[14], (const float*)d_in[15],
            (const float*)d_in[16], (const float*)d_in[17],
            s2, t, y1);
    // mid: relu(inorm(s2)) -> s1
    inorm_kernel<2><<<BB * CC, 256>>>(s2, s1, nullptr);
    // grapher 2: s1 -> s2
    run_grapher(s1, rp,
                (const float*)d_in[8],  (const float*)d_in[9],
                (const float*)d_in[10], (const float*)d_in[11],
                (const float*)d_in[12], (const float*)d_in[13],
                s2, y1, y1t, xnt, xtf, cd, idx, cat, y2, t);
    // ffn 2: s2 -> s1
    run_ffn(s2,
            (const float*)d_in[18], (const float*)d_in[19],
            (const float*)d_in[20], (const float*)d_in[21],
            s1, t, y1);
    // final: out = X0 + inorm(s1)
    inorm_kernel<3><<<BB * CC, 256>>>(s1, (float*)d_out, X0);
}